// round 1
// baseline (speedup 1.0000x reference)
#include <cuda_runtime.h>
#include <math.h>

#define NT 256
#define STR 68          // padded row stride (floats): 16B-aligned rows, conflict-free col loads
#define MAT (64*STR)    // floats per smem matrix buffer

// ---- packed f32x2 helpers (sm_100+) ----
union F2 { unsigned long long u; float2 f; };

__device__ __forceinline__ unsigned long long fma2(unsigned long long a,
                                                   unsigned long long b,
                                                   unsigned long long c) {
    unsigned long long d;
    asm("fma.rn.f32x2 %0, %1, %2, %3;" : "=l"(d) : "l"(a), "l"(b), "l"(c));
    return d;
}
__device__ __forceinline__ unsigned long long pack2(float x) {
    unsigned long long u;
    asm("mov.b64 %0, {%1, %1};" : "=l"(u) : "f"(x));
    return u;
}

// C = Sa @ Sb (64x64), thread tile 4x4 as 8 f32x2 accumulators.
// MODE 0: Sc = acc
// MODE 1: Sc = 1.5*I - 0.5*acc        (the 0.5*(3I - ZY) step)
// MODE 2: gout = scale * acc          (final write to global, row-major 64)
template<int MODE>
__device__ __forceinline__ void mm64(const float* __restrict__ Sa,
                                     const float* __restrict__ Sb,
                                     float* __restrict__ Sc,
                                     float* __restrict__ gout,
                                     float scale, int ty, int tx)
{
    F2 acc[4][2];
#pragma unroll
    for (int i = 0; i < 4; i++) { acc[i][0].u = 0ull; acc[i][1].u = 0ull; }

    const int r0 = ty * 4;
    const int c0 = tx * 4;

#pragma unroll 8
    for (int k = 0; k < 64; k++) {
        F2 b0, b1;
        b0.f = *(const float2*)(Sb + k * STR + c0);
        b1.f = *(const float2*)(Sb + k * STR + c0 + 2);
#pragma unroll
        for (int i = 0; i < 4; i++) {
            unsigned long long ap = pack2(Sa[(r0 + i) * STR + k]);
            acc[i][0].u = fma2(ap, b0.u, acc[i][0].u);
            acc[i][1].u = fma2(ap, b1.u, acc[i][1].u);
        }
    }

    // all reads of Sa/Sb (and any in-place destination) are done before writes
    __syncthreads();

#pragma unroll
    for (int i = 0; i < 4; i++) {
        const int r = r0 + i;
        float2 v0 = acc[i][0].f, v1 = acc[i][1].f;
        if (MODE == 1) {
            v0.x = (r == c0     ? 1.5f : 0.0f) - 0.5f * v0.x;
            v0.y = (r == c0 + 1 ? 1.5f : 0.0f) - 0.5f * v0.y;
            v1.x = (r == c0 + 2 ? 1.5f : 0.0f) - 0.5f * v1.x;
            v1.y = (r == c0 + 3 ? 1.5f : 0.0f) - 0.5f * v1.y;
        }
        if (MODE == 2) {
            float4 o = make_float4(v0.x * scale, v0.y * scale,
                                   v1.x * scale, v1.y * scale);
            *(float4*)(gout + r * 64 + c0) = o;
        } else {
            *(float2*)(Sc + r * STR + c0)     = v0;
            *(float2*)(Sc + r * STR + c0 + 2) = v1;
        }
    }
    if (MODE != 2) __syncthreads();
}

__global__ void __launch_bounds__(NT)
isqrtm_kernel(const float* __restrict__ x, float* __restrict__ out)
{
    extern __shared__ float sm[];
    float* SA  = sm;                 // A, then reused as T
    float* SY  = sm + MAT;
    float* SZ  = sm + 2 * MAT;
    float* red = sm + 3 * MAT;       // 65 floats for trace reduction

    const int b   = blockIdx.x;
    const int tid = threadIdx.x;
    const float* X = x   + (size_t)b * 4096;
    float*       O = out + (size_t)b * 4096;

    // load 64x64 tile (float4) into padded smem
    for (int i = tid; i < 1024; i += NT) {
        float4 v = ((const float4*)X)[i];
        int r = i >> 4;
        int c = (i & 15) * 4;
        *(float4*)(SA + r * STR + c) = v;
    }
    __syncthreads();

    // normA = trace(x)
    if (tid < 64) red[tid] = SA[tid * STR + tid];
    __syncthreads();
    if (tid == 0) {
        float s = 0.f;
#pragma unroll
        for (int i = 0; i < 64; i++) s += red[i];
        red[64] = s;
    }
    __syncthreads();
    const float normA = red[64];
    const float inv   = 1.0f / normA;

    const int ty = tid >> 4, tx = tid & 15;

    // A = x / normA ; Z = 0.5*(3I - A)
#pragma unroll
    for (int i = 0; i < 4; i++) {
        const int r = ty * 4 + i;
#pragma unroll
        for (int j = 0; j < 4; j++) {
            const int c = tx * 4 + j;
            float a = SA[r * STR + c] * inv;
            SA[r * STR + c] = a;
            SZ[r * STR + c] = 0.5f * ((r == c ? 3.0f : 0.0f) - a);
        }
    }
    __syncthreads();

    // Y = A @ Z
    mm64<0>(SA, SZ, SY, nullptr, 0.f, ty, tx);

#pragma unroll 1
    for (int it = 0; it < 4; ++it) {
        // T = 0.5*(3I - Z@Y)   (T lives in SA)
        mm64<1>(SZ, SY, SA, nullptr, 0.f, ty, tx);
        if (it < 3) {
            mm64<0>(SY, SA, SY, nullptr, 0.f, ty, tx);   // Y = Y @ T
            mm64<0>(SA, SZ, SZ, nullptr, 0.f, ty, tx);   // Z = T @ Z
        } else {
            // out = sqrt(normA) * (Y @ T)   == sqrt(normA) * 0.5 * Y @ (3I - Z@Y)
            mm64<2>(SY, SA, nullptr, O, sqrtf(normA), ty, tx);
        }
    }
}

extern "C" void kernel_launch(void* const* d_in, const int* in_sizes, int n_in,
                              void* d_out, int out_size)
{
    const float* x = (const float*)d_in[0];
    float* out = (float*)d_out;

    const int batches = in_sizes[0] / 4096;   // 8192
    const int smem_bytes = (3 * MAT + 80) * sizeof(float);   // 52.5 KB

    cudaFuncSetAttribute(isqrtm_kernel,
                         cudaFuncAttributeMaxDynamicSharedMemorySize, smem_bytes);
    isqrtm_kernel<<<batches, NT, smem_bytes>>>(x, out);
}

// round 5
// speedup vs baseline: 2.4625x; 2.4625x over previous
#include <cuda_runtime.h>
#include <cuda_fp16.h>
#include <math.h>
#include <stdint.h>

#define NT 128
#define BUF 8192                       // one 64x64 fp16 buffer: 64 rows x 128B
#define SMEM_TOTAL (6*BUF + 64)
// buffer roles: 0,1 = Y splits ; 2,3 = Z splits ; 4,5 = T/A splits

__device__ __forceinline__ uint32_t swz(uint32_t b) { return b ^ ((b >> 3) & 0x70); }

__device__ __forceinline__ uint32_t smem_u32(const void* p) {
    uint32_t a;
    asm("{ .reg .u64 t; cvta.to.shared.u64 t, %1; cvt.u32.u64 %0, t; }" : "=r"(a) : "l"(p));
    return a;
}

__device__ __forceinline__ void ldsm4(uint32_t* r, uint32_t addr) {
    asm volatile("ldmatrix.sync.aligned.m8n8.x4.shared.b16 {%0,%1,%2,%3}, [%4];"
                 : "=r"(r[0]), "=r"(r[1]), "=r"(r[2]), "=r"(r[3]) : "r"(addr));
}

__device__ __forceinline__ void mma16816(float* c, const uint32_t* a, const uint32_t* b) {
    asm volatile("mma.sync.aligned.m16n8k16.row.col.f32.f16.f16.f32 "
                 "{%0,%1,%2,%3}, {%4,%5,%6,%7}, {%8,%9}, {%0,%1,%2,%3};"
                 : "+f"(c[0]), "+f"(c[1]), "+f"(c[2]), "+f"(c[3])
                 : "r"(a[0]), "r"(a[1]), "r"(a[2]), "r"(a[3]), "r"(b[0]), "r"(b[1]));
}

// fp32 -> 2-term fp16 split
__device__ __forceinline__ void split2(float v, __half& h1, __half& h2) {
    h1 = __float2half_rn(v);
    h2 = __float2half_rn(v - __half2float(h1));
}
__device__ __forceinline__ uint32_t packh(__half a, __half b) {
    __half2 t; t.x = a; t.y = b;
    return *reinterpret_cast<uint32_t*>(&t);
}

// D = Ma @ Mb (64x64, both symmetric -> row.col works transpose-free).
// Ma = a1+a2 (fp16 splits in smem), Mb = b1+b2. 3 products: a1b1, a1b2, a2b1.
// MODE 0: dst = D   MODE 1: dst = 1.5I - 0.5 D   MODE 2: gmem O = scale*D
template <int MODE>
__device__ __forceinline__ void gemm64(uint32_t sbase, char* smem,
                                       int a1, int a2, int b1, int b2,
                                       int d1, int d2,
                                       float* __restrict__ O, float scale,
                                       int wid, int lane)
{
    __syncthreads();   // operands from previous epilogue are visible

    const int m0 = wid * 16;

    // ---- A fragments: rows m0..m0+15, both splits, 4 k-tiles ----
    uint32_t A1[4][4], A2[4][4];
    {
        const int ar = m0 + (lane & 15);
        const int ac = (lane >> 4) * 16;      // 16B column within k-tile
#pragma unroll
        for (int kt = 0; kt < 4; ++kt) {
            uint32_t rel = swz((uint32_t)(ar * 128 + kt * 32 + ac));
            ldsm4(A1[kt], sbase + a1 + rel);
            ldsm4(A2[kt], sbase + a2 + rel);
        }
    }

    float acc[8][4];
#pragma unroll
    for (int j = 0; j < 8; ++j)
#pragma unroll
        for (int q = 0; q < 4; ++q) acc[j][q] = 0.0f;

    // ---- B fragments per n-tile; ldmatrix.x4 packs (ktile, k-half) ----
    const int bl = lane & 7;
    const int bg = lane >> 3;                 // 0..3 -> (ktile offset, half)
    const uint32_t bcol = (uint32_t)((bg >> 1) * 32 + (bg & 1) * 16);

#pragma unroll
    for (int j = 0; j < 8; ++j) {
        const uint32_t rowb = (uint32_t)((j * 8 + bl) * 128);
        uint32_t r01 = swz(rowb + bcol);            // ktiles 0,1
        uint32_t r23 = swz(rowb + 64 + bcol);       // ktiles 2,3 (+2*32B)
        uint32_t Bx[4], By[4], Cx[4], Cy[4];
        ldsm4(Bx, sbase + b1 + r01);
        ldsm4(By, sbase + b1 + r23);
        ldsm4(Cx, sbase + b2 + r01);
        ldsm4(Cy, sbase + b2 + r23);
        const uint32_t* B1f[4] = {Bx, Bx + 2, By, By + 2};
        const uint32_t* B2f[4] = {Cx, Cx + 2, Cy, Cy + 2};
#pragma unroll
        for (int kt = 0; kt < 4; ++kt) {
            mma16816(acc[j], A1[kt], B1f[kt]);
            mma16816(acc[j], A1[kt], B2f[kt]);
            mma16816(acc[j], A2[kt], B1f[kt]);
        }
    }

    __syncthreads();   // all reads done before in-place writes

    // ---- epilogue: transform, split, store ----
    const int gr = lane >> 2, qp = lane & 3;
#pragma unroll
    for (int j = 0; j < 8; ++j) {
        const int colb = j * 8 + 2 * qp;
#pragma unroll
        for (int half = 0; half < 2; ++half) {
            const int row = m0 + gr + half * 8;
            float v0 = acc[j][half * 2 + 0];
            float v1 = acc[j][half * 2 + 1];
            if (MODE == 1) {
                v0 = (colb     == row ? 1.5f : 0.0f) - 0.5f * v0;
                v1 = (colb + 1 == row ? 1.5f : 0.0f) - 0.5f * v1;
            }
            if (MODE == 2) {
                *(float2*)(O + row * 64 + colb) = make_float2(v0 * scale, v1 * scale);
            } else {
                __half p0, q0, p1, q1;
                split2(v0, p0, q0);
                split2(v1, p1, q1);
                uint32_t off = swz((uint32_t)(row * 128 + colb * 2));
                *(uint32_t*)(smem + d1 + off) = packh(p0, p1);
                *(uint32_t*)(smem + d2 + off) = packh(q0, q1);
            }
        }
    }
}

__global__ void __launch_bounds__(NT, 4)
isqrtm_hmma_kernel(const float* __restrict__ x, float* __restrict__ out)
{
    extern __shared__ char smem[];
    const uint32_t sbase = smem_u32(smem);
    float* red = (float*)(smem + 6 * BUF);

    const int tid = threadIdx.x;
    const int wid = tid >> 5, lane = tid & 31;
    const int b = blockIdx.x;
    const float* X = x + (size_t)b * 4096;
    float* O = out + (size_t)b * 4096;

    // ---- trace(X) ----
    float tr = (tid < 64) ? __ldg(X + tid * 65) : 0.0f;
#pragma unroll
    for (int o = 16; o; o >>= 1) tr += __shfl_xor_sync(0xFFFFFFFFu, tr, o);
    if (lane == 0) red[wid] = tr;
    __syncthreads();
    const float normA = red[0] + red[1];
    const float inv = 1.0f / normA;
    const float sq  = sqrtf(normA);
    __syncthreads();

    // ---- prologue: A = X/normA -> bufs 4,5 ; Z = 1.5I - 0.5A -> bufs 2,3 ----
    {
        const int r  = tid >> 1;
        const int c0 = (tid & 1) * 32;
#pragma unroll
        for (int q = 0; q < 16; ++q) {
            const int c = c0 + 2 * q;
            float2 f = *(const float2*)(X + r * 64 + c);
            float a0 = f.x * inv, a1 = f.y * inv;
            float z0 = (c     == r ? 1.5f : 0.0f) - 0.5f * a0;
            float z1 = (c + 1 == r ? 1.5f : 0.0f) - 0.5f * a1;
            __half p0, s0, p1, s1;
            uint32_t off = swz((uint32_t)(r * 128 + c * 2));
            split2(a0, p0, s0); split2(a1, p1, s1);
            *(uint32_t*)(smem + 4 * BUF + off) = packh(p0, p1);
            *(uint32_t*)(smem + 5 * BUF + off) = packh(s0, s1);
            split2(z0, p0, s0); split2(z1, p1, s1);
            *(uint32_t*)(smem + 2 * BUF + off) = packh(p0, p1);
            *(uint32_t*)(smem + 3 * BUF + off) = packh(s0, s1);
        }
    }

    // ---- Newton-Schulz chain (12 GEMMs) ----
    // Y = A @ Z
    gemm64<0>(sbase, smem, 4*BUF, 5*BUF, 2*BUF, 3*BUF, 0*BUF, 1*BUF, O, 0.f, wid, lane);
#pragma unroll 1
    for (int it = 0; it < 3; ++it) {
        // T = 1.5I - 0.5 * Z@Y
        gemm64<1>(sbase, smem, 2*BUF, 3*BUF, 0*BUF, 1*BUF, 4*BUF, 5*BUF, O, 0.f, wid, lane);
        // Y = Y @ T
        gemm64<0>(sbase, smem, 0*BUF, 1*BUF, 4*BUF, 5*BUF, 0*BUF, 1*BUF, O, 0.f, wid, lane);
        // Z = T @ Z
        gemm64<0>(sbase, smem, 4*BUF, 5*BUF, 2*BUF, 3*BUF, 2*BUF, 3*BUF, O, 0.f, wid, lane);
    }
    // T = 1.5I - 0.5 * Z@Y ; out = sqrt(normA) * (Y @ T)
    gemm64<1>(sbase, smem, 2*BUF, 3*BUF, 0*BUF, 1*BUF, 4*BUF, 5*BUF, O, 0.f, wid, lane);
    gemm64<2>(sbase, smem, 0*BUF, 1*BUF, 4*BUF, 5*BUF, 0, 0, O, sq, wid, lane);
}

extern "C" void kernel_launch(void* const* d_in, const int* in_sizes, int n_in,
                              void* d_out, int out_size)
{
    const float* x = (const float*)d_in[0];
    float* out = (float*)d_out;
    const int batches = in_sizes[0] / 4096;

    cudaFuncSetAttribute(isqrtm_hmma_kernel,
                         cudaFuncAttributeMaxDynamicSharedMemorySize, SMEM_TOTAL);
    isqrtm_hmma_kernel<<<batches, NT, SMEM_TOTAL>>>(x, out);
}

// round 7
// speedup vs baseline: 2.8058x; 1.1394x over previous
#include <cuda_runtime.h>
#include <cuda_fp16.h>
#include <math.h>
#include <stdint.h>

#define NT 128
#define BUF 8192                       // one 64x64 fp16 buffer: 64 rows x 128B
#define SMEM_TOTAL (6*BUF + 64)
// buffer roles: 0,1 = Y splits ; 2,3 = Z splits ; 4,5 = T/A splits

__device__ __forceinline__ uint32_t swz(uint32_t b) { return b ^ ((b >> 3) & 0x70); }

__device__ __forceinline__ uint32_t smem_u32(const void* p) {
    uint32_t a;
    asm("{ .reg .u64 t; cvta.to.shared.u64 t, %1; cvt.u32.u64 %0, t; }" : "=r"(a) : "l"(p));
    return a;
}

__device__ __forceinline__ void ldsm4(uint32_t* r, uint32_t addr) {
    asm volatile("ldmatrix.sync.aligned.m8n8.x4.shared.b16 {%0,%1,%2,%3}, [%4];"
                 : "=r"(r[0]), "=r"(r[1]), "=r"(r[2]), "=r"(r[3]) : "r"(addr));
}

__device__ __forceinline__ void mma16816(float* c, const uint32_t* a, const uint32_t* b) {
    asm volatile("mma.sync.aligned.m16n8k16.row.col.f32.f16.f16.f32 "
                 "{%0,%1,%2,%3}, {%4,%5,%6,%7}, {%8,%9}, {%0,%1,%2,%3};"
                 : "+f"(c[0]), "+f"(c[1]), "+f"(c[2]), "+f"(c[3])
                 : "r"(a[0]), "r"(a[1]), "r"(a[2]), "r"(a[3]), "r"(b[0]), "r"(b[1]));
}

// fp32 -> 2-term fp16 split
__device__ __forceinline__ void split2(float v, __half& h1, __half& h2) {
    h1 = __float2half_rn(v);
    h2 = __float2half_rn(v - __half2float(h1));
}
__device__ __forceinline__ uint32_t packh(__half a, __half b) {
    __half2 t; t.x = a; t.y = b;
    return *reinterpret_cast<uint32_t*>(&t);
}

// D = Ma @ Mb (64x64, both symmetric -> row.col is transpose-free).
// Ma = a1+a2 (fp16 splits), Mb = b1+b2. 3 products: a1b1, a1b2, a2b1.
// Warp grid 2x2: warp (wm, wn) computes rows 32wm..+31, cols 32wn..+31.
// A-frags and B-frags are each duplicated across only 2 warps (vs 4 before).
// MODE 0: dst = D   MODE 1: dst = 1.5I - 0.5 D   MODE 2: gmem O = scale*D
template <int MODE>
__device__ __forceinline__ void gemm64(uint32_t sbase, char* smem,
                                       int a1, int a2, int b1, int b2,
                                       int d1, int d2,
                                       float* __restrict__ O, float scale,
                                       int wm, int wn, int lane)
{
    __syncthreads();   // operands from previous epilogue are visible

    float acc[2][4][4];
#pragma unroll
    for (int mt = 0; mt < 2; ++mt)
#pragma unroll
        for (int j = 0; j < 4; ++j)
#pragma unroll
            for (int q = 0; q < 4; ++q) acc[mt][j][q] = 0.0f;

    const int arow = wm * 32 + (lane & 15);
    const int acol = (lane >> 4) * 16;

    const int bl = lane & 7;
    const int bg = lane >> 3;                       // ldsm.x4 quadrant
    const uint32_t bcol = (uint32_t)((bg >> 1) * 32 + (bg & 1) * 16);

#pragma unroll
    for (int ktp = 0; ktp < 2; ++ktp) {
        // ---- A fragments for this k-tile pair: [spl][mt][ktl] ----
        uint32_t A1[2][2][4], A2[2][2][4];
#pragma unroll
        for (int mt = 0; mt < 2; ++mt)
#pragma unroll
            for (int ktl = 0; ktl < 2; ++ktl) {
                uint32_t rel = swz((uint32_t)((arow + mt * 16) * 128 +
                                              ktp * 64 + ktl * 32 + acol));
                ldsm4(A1[mt][ktl], sbase + a1 + rel);
                ldsm4(A2[mt][ktl], sbase + a2 + rel);
            }

        // ---- B per n-tile: one ldsm.x4 covers both k-tiles of the pair ----
#pragma unroll
        for (int j = 0; j < 4; ++j) {
            const uint32_t rowb = (uint32_t)((wn * 32 + j * 8 + bl) * 128);
            uint32_t rel = swz(rowb + ktp * 64 + bcol);
            uint32_t Bx[4], Cx[4];
            ldsm4(Bx, sbase + b1 + rel);   // split1: regs 0,1 = kt_lo ; 2,3 = kt_hi
            ldsm4(Cx, sbase + b2 + rel);   // split2
#pragma unroll
            for (int ktl = 0; ktl < 2; ++ktl) {
#pragma unroll
                for (int mt = 0; mt < 2; ++mt) {
                    mma16816(acc[mt][j], A1[mt][ktl], Bx + 2 * ktl);
                    mma16816(acc[mt][j], A1[mt][ktl], Cx + 2 * ktl);
                    mma16816(acc[mt][j], A2[mt][ktl], Bx + 2 * ktl);
                }
            }
        }
    }

    __syncthreads();   // all reads done before in-place writes

    // ---- epilogue: transform, split, store ----
    const int gr = lane >> 2, qp = lane & 3;
#pragma unroll
    for (int mt = 0; mt < 2; ++mt)
#pragma unroll
    for (int j = 0; j < 4; ++j) {
        const int colb = wn * 32 + j * 8 + 2 * qp;
#pragma unroll
        for (int half = 0; half < 2; ++half) {
            const int row = wm * 32 + mt * 16 + gr + half * 8;
            float v0 = acc[mt][j][half * 2 + 0];
            float v1 = acc[mt][j][half * 2 + 1];
            if (MODE == 1) {
                v0 = (colb     == row ? 1.5f : 0.0f) - 0.5f * v0;
                v1 = (colb + 1 == row ? 1.5f : 0.0f) - 0.5f * v1;
            }
            if (MODE == 2) {
                *(float2*)(O + row * 64 + colb) = make_float2(v0 * scale, v1 * scale);
            } else {
                __half p0, q0, p1, q1;
                split2(v0, p0, q0);
                split2(v1, p1, q1);
                uint32_t off = swz((uint32_t)(row * 128 + colb * 2));
                *(uint32_t*)(smem + d1 + off) = packh(p0, p1);
                *(uint32_t*)(smem + d2 + off) = packh(q0, q1);
            }
        }
    }
}

__global__ void __launch_bounds__(NT, 4)
isqrtm_hmma_kernel(const float* __restrict__ x, float* __restrict__ out)
{
    extern __shared__ char smem[];
    const uint32_t sbase = smem_u32(smem);
    float* red = (float*)(smem + 6 * BUF);

    const int tid = threadIdx.x;
    const int wid = tid >> 5, lane = tid & 31;
    const int wm = wid >> 1, wn = wid & 1;
    const int b = blockIdx.x;
    const float* X = x + (size_t)b * 4096;
    float* O = out + (size_t)b * 4096;

    // ---- trace(X) ----
    float tr = (tid < 64) ? __ldg(X + tid * 65) : 0.0f;
#pragma unroll
    for (int o = 16; o; o >>= 1) tr += __shfl_xor_sync(0xFFFFFFFFu, tr, o);
    if (lane == 0) red[wid] = tr;
    __syncthreads();
    const float normA = red[0] + red[1];
    const float inv = 1.0f / normA;
    const float sq  = sqrtf(normA);
    __syncthreads();

    // ---- prologue: A = X/normA -> bufs 4,5 ; Z = 1.5I - 0.5A -> bufs 2,3 ----
    {
        const int r  = tid >> 1;
        const int c0 = (tid & 1) * 32;
#pragma unroll
        for (int q = 0; q < 16; ++q) {
            const int c = c0 + 2 * q;
            float2 f = *(const float2*)(X + r * 64 + c);
            float a0 = f.x * inv, a1 = f.y * inv;
            float z0 = (c     == r ? 1.5f : 0.0f) - 0.5f * a0;
            float z1 = (c + 1 == r ? 1.5f : 0.0f) - 0.5f * a1;
            __half p0, s0, p1, s1;
            uint32_t off = swz((uint32_t)(r * 128 + c * 2));
            split2(a0, p0, s0); split2(a1, p1, s1);
            *(uint32_t*)(smem + 4 * BUF + off) = packh(p0, p1);
            *(uint32_t*)(smem + 5 * BUF + off) = packh(s0, s1);
            split2(z0, p0, s0); split2(z1, p1, s1);
            *(uint32_t*)(smem + 2 * BUF + off) = packh(p0, p1);
            *(uint32_t*)(smem + 3 * BUF + off) = packh(s0, s1);
        }
    }

    // ---- Newton-Schulz chain (12 GEMMs) ----
    // Y = A @ Z
    gemm64<0>(sbase, smem, 4*BUF, 5*BUF, 2*BUF, 3*BUF, 0*BUF, 1*BUF, O, 0.f, wm, wn, lane);
#pragma unroll 1
    for (int it = 0; it < 3; ++it) {
        // T = 1.5I - 0.5 * Z@Y
        gemm64<1>(sbase, smem, 2*BUF, 3*BUF, 0*BUF, 1*BUF, 4*BUF, 5*BUF, O, 0.f, wm, wn, lane);
        // Y = Y @ T
        gemm64<0>(sbase, smem, 0*BUF, 1*BUF, 4*BUF, 5*BUF, 0*BUF, 1*BUF, O, 0.f, wm, wn, lane);
        // Z = T @ Z
        gemm64<0>(sbase, smem, 4*BUF, 5*BUF, 2*BUF, 3*BUF, 2*BUF, 3*BUF, O, 0.f, wm, wn, lane);
    }
    // T = 1.5I - 0.5 * Z@Y ; out = sqrt(normA) * (Y @ T)
    gemm64<1>(sbase, smem, 2*BUF, 3*BUF, 0*BUF, 1*BUF, 4*BUF, 5*BUF, O, 0.f, wm, wn, lane);
    gemm64<2>(sbase, smem, 0*BUF, 1*BUF, 4*BUF, 5*BUF, 0, 0, O, sq, wm, wn, lane);
}

extern "C" void kernel_launch(void* const* d_in, const int* in_sizes, int n_in,
                              void* d_out, int out_size)
{
    const float* x = (const float*)d_in[0];
    float* out = (float*)d_out;
    const int batches = in_sizes[0] / 4096;

    cudaFuncSetAttribute(isqrtm_hmma_kernel,
                         cudaFuncAttributeMaxDynamicSharedMemorySize, SMEM_TOTAL);
    isqrtm_hmma_kernel<<<batches, NT, SMEM_TOTAL>>>(x, out);
}